// round 2
// baseline (speedup 1.0000x reference)
#include <cuda_runtime.h>

#define B_ 2
#define S_ 2048
#define D_ 1024
#define H_ 16
#define DH_ 64
#define NROW (B_ * S_)   // 4096

// Scratch for projected Q/K/V in [B,H,S,DH] layout (16 MB each)
__device__ float g_q[B_ * H_ * S_ * DH_];
__device__ float g_k[B_ * H_ * S_ * DH_];
__device__ float g_v[B_ * H_ * S_ * DH_];

// ---------------------------------------------------------------------------
// Projection GEMM: out[n,d] = sum_k x[n,k] * w[k,d] + bias[d]
// 64x64 tile per block, 256 threads, 4x4 micro-tile per thread.
// Output written directly in [B,H,S,DH] layout (a 64-col tile == one head).
// ---------------------------------------------------------------------------
__global__ __launch_bounds__(256) void proj_kernel(
    const float* __restrict__ x, const float* __restrict__ w,
    const float* __restrict__ bias, float* __restrict__ out)
{
    __shared__ float As[64][17];   // pad 17: conflict-free column reads
    __shared__ float Bs[16][64];

    const int tid = threadIdx.x;
    const int tx = tid & 15, ty = tid >> 4;
    const int row0 = blockIdx.y * 64;
    const int col0 = blockIdx.x * 64;

    float acc[4][4] = {};

    for (int k0 = 0; k0 < D_; k0 += 16) {
        #pragma unroll
        for (int l = 0; l < 4; l++) {
            int idx = tid + l * 256;          // 0..1023
            int ra = idx >> 4, ca = idx & 15;
            As[ra][ca] = x[(row0 + ra) * D_ + k0 + ca];
            int rb = idx >> 6, cb = idx & 63;
            Bs[rb][cb] = w[(k0 + rb) * D_ + col0 + cb];
        }
        __syncthreads();

        #pragma unroll
        for (int kk = 0; kk < 16; kk++) {
            float4 b4 = *(const float4*)&Bs[kk][tx * 4];
            float b[4] = {b4.x, b4.y, b4.z, b4.w};
            float a[4];
            #pragma unroll
            for (int i = 0; i < 4; i++) a[i] = As[ty * 4 + i][kk];
            #pragma unroll
            for (int i = 0; i < 4; i++)
                #pragma unroll
                for (int j = 0; j < 4; j++)
                    acc[i][j] = fmaf(a[i], b[j], acc[i][j]);
        }
        __syncthreads();
    }

    // bias + store to [B,H,S,DH]; col0 is a multiple of 64 => one head per tile
    const int h = col0 >> 6;
    #pragma unroll
    for (int i = 0; i < 4; i++) {
        int n  = row0 + ty * 4 + i;
        int b_ = n >> 11;           // n / S_
        int s  = n & (S_ - 1);
        float* dst = out + (((b_ * H_ + h) * S_) + s) * DH_ + tx * 4;
        #pragma unroll
        for (int j = 0; j < 4; j++)
            dst[j] = acc[i][j] + bias[col0 + tx * 4 + j];
    }
}

// ---------------------------------------------------------------------------
// Flash attention (fp32, online softmax).
// Block = one (b,h) x 64 query rows. 256 threads, 4x4 per thread.
// Column mapping j = tx + 16*jj so every LDS pattern is bank-conflict-free
// (row stride 65 == 1 mod 32). K tile and P tile share one smem buffer.
// ---------------------------------------------------------------------------
__global__ __launch_bounds__(256) void attn_kernel(
    const float* __restrict__ gq, const float* __restrict__ gk,
    const float* __restrict__ gv, float* __restrict__ out)
{
    extern __shared__ float sm[];
    float* Qs = sm;                 // [64][64]
    float* KP = sm + 64 * 64;       // [64][65]  (K tile, then reused as P tile)
    float* Vs = KP + 64 * 65;       // [64][64]

    const int tid = threadIdx.x;
    const int tx = tid & 15, ty = tid >> 4;
    const int bh = blockIdx.y;                 // 0..31  (b*16 + h)
    const int q0 = blockIdx.x * 64;

    // Load Q tile once
    const int base_q = (bh * S_ + q0) * DH_;
    #pragma unroll
    for (int l = 0; l < 16; l++) {
        int idx = tid + l * 256;
        Qs[idx] = gq[base_q + idx];
    }

    float m[4], lsum[4], acc[4][4];
    #pragma unroll
    for (int i = 0; i < 4; i++) {
        m[i] = -1e30f; lsum[i] = 0.0f;
        #pragma unroll
        for (int c = 0; c < 4; c++) acc[i][c] = 0.0f;
    }

    for (int kt = 0; kt < S_ / 64; kt++) {
        const int base_k = (bh * S_ + kt * 64) * DH_;
        #pragma unroll
        for (int l = 0; l < 16; l++) {
            int idx = tid + l * 256;
            int r = idx >> 6, c = idx & 63;
            KP[r * 65 + c] = gk[base_k + idx];
            Vs[idx]        = gv[base_k + idx];
        }
        __syncthreads();

        // scores: s[i][jj] = dot(Q[row_i], K[col_j]) / 8
        float s[4][4];
        #pragma unroll
        for (int i = 0; i < 4; i++)
            #pragma unroll
            for (int j = 0; j < 4; j++) s[i][j] = 0.0f;

        #pragma unroll 8
        for (int d = 0; d < 64; d++) {
            float a[4], b[4];
            #pragma unroll
            for (int i = 0; i < 4; i++) a[i] = Qs[(ty * 4 + i) * 64 + d];
            #pragma unroll
            for (int j = 0; j < 4; j++) b[j] = KP[(tx + 16 * j) * 65 + d];
            #pragma unroll
            for (int i = 0; i < 4; i++)
                #pragma unroll
                for (int j = 0; j < 4; j++)
                    s[i][j] = fmaf(a[i], b[j], s[i][j]);
        }

        // online softmax update (per-row, rows owned by ty-group of 16 lanes)
        #pragma unroll
        for (int i = 0; i < 4; i++) {
            float mx = s[i][0];
            #pragma unroll
            for (int j = 1; j < 4; j++) mx = fmaxf(mx, s[i][j]);
            mx *= 0.125f;
            #pragma unroll
            for (int off = 1; off < 16; off <<= 1)
                mx = fmaxf(mx, __shfl_xor_sync(0xffffffffu, mx, off));
            float mnew  = fmaxf(m[i], mx);
            float alpha = __expf(m[i] - mnew);
            float rs = 0.0f;
            #pragma unroll
            for (int j = 0; j < 4; j++) {
                s[i][j] = __expf(fmaf(s[i][j], 0.125f, -mnew));
                rs += s[i][j];
            }
            #pragma unroll
            for (int off = 1; off < 16; off <<= 1)
                rs += __shfl_xor_sync(0xffffffffu, rs, off);
            lsum[i] = lsum[i] * alpha + rs;
            m[i] = mnew;
            #pragma unroll
            for (int c = 0; c < 4; c++) acc[i][c] *= alpha;
        }

        __syncthreads();   // everyone done reading K before overwrite with P
        #pragma unroll
        for (int i = 0; i < 4; i++)
            #pragma unroll
            for (int j = 0; j < 4; j++)
                KP[(ty * 4 + i) * 65 + tx + 16 * j] = s[i][j];
        __syncthreads();

        // O += P @ V
        #pragma unroll 8
        for (int j = 0; j < 64; j++) {
            float p[4], v[4];
            #pragma unroll
            for (int i = 0; i < 4; i++) p[i] = KP[(ty * 4 + i) * 65 + j];
            #pragma unroll
            for (int c = 0; c < 4; c++) v[c] = Vs[j * 64 + tx + 16 * c];
            #pragma unroll
            for (int i = 0; i < 4; i++)
                #pragma unroll
                for (int c = 0; c < 4; c++)
                    acc[i][c] = fmaf(p[i], v[c], acc[i][c]);
        }
        __syncthreads();
    }

    // normalize + store to [B,S,D] output
    const int b_ = bh >> 4, h = bh & 15;
    #pragma unroll
    for (int i = 0; i < 4; i++) {
        int srow = q0 + ty * 4 + i;
        float inv = 1.0f / lsum[i];
        float* dst = out + (b_ * S_ + srow) * D_ + h * DH_;
        #pragma unroll
        for (int c = 0; c < 4; c++)
            dst[tx + 16 * c] = acc[i][c] * inv;
    }
}

// ---------------------------------------------------------------------------
extern "C" void kernel_launch(void* const* d_in, const int* in_sizes, int n_in,
                              void* d_out, int out_size)
{
    const float* vq = (const float*)d_in[0];
    const float* vk = (const float*)d_in[1];
    const float* vv = (const float*)d_in[2];
    const float* wq = (const float*)d_in[3];
    const float* bq = (const float*)d_in[4];
    const float* wk = (const float*)d_in[5];
    const float* bk = (const float*)d_in[6];
    const float* wv = (const float*)d_in[7];
    const float* bv = (const float*)d_in[8];
    float* out = (float*)d_out;

    void *pq, *pk, *pv;
    cudaGetSymbolAddress(&pq, g_q);
    cudaGetSymbolAddress(&pk, g_k);
    cudaGetSymbolAddress(&pv, g_v);

    dim3 grid_p(D_ / 64, NROW / 64);   // (16, 64)
    proj_kernel<<<grid_p, 256>>>(vq, wq, bq, (float*)pq);
    proj_kernel<<<grid_p, 256>>>(vk, wk, bk, (float*)pk);
    proj_kernel<<<grid_p, 256>>>(vv, wv, bv, (float*)pv);

    const int smem_bytes = (64 * 64 + 64 * 65 + 64 * 64) * 4;   // 49408
    cudaFuncSetAttribute(attn_kernel,
                         cudaFuncAttributeMaxDynamicSharedMemorySize, smem_bytes);
    dim3 grid_a(S_ / 64, B_ * H_);     // (32, 32)
    attn_kernel<<<grid_a, 256, smem_bytes>>>((const float*)pq, (const float*)pk,
                                             (const float*)pv, out);
}

// round 4
// speedup vs baseline: 1.2809x; 1.2809x over previous
#include <cuda_runtime.h>
#include <cuda_bf16.h>
#include <cstdint>

#define B_ 2
#define S_ 2048
#define D_ 1024
#define H_ 16
#define DH_ 64
#define NROW (B_ * S_)   // 4096

// Scratch for projected Q/K/V in [B,H,S,DH] layout
__device__ float g_q[B_ * H_ * S_ * DH_];
__device__ float g_k[B_ * H_ * S_ * DH_];
__device__ float g_v[B_ * H_ * S_ * DH_];

// ---------------------------------------------------------------------------
// Warp-level bf16 MMA (family-common HMMA path; tcgen05 is unavailable at the
// harness's compute_103 PTX target).
// D[16x8] += A[16x16] * B[16x8], fp32 accum.
// ---------------------------------------------------------------------------
__device__ __forceinline__ void mma16816(float* c, const uint32_t* a, const uint32_t* b) {
    asm volatile(
        "mma.sync.aligned.m16n8k16.row.col.f32.bf16.bf16.f32 "
        "{%0,%1,%2,%3}, {%4,%5,%6,%7}, {%8,%9}, {%0,%1,%2,%3};"
        : "+f"(c[0]), "+f"(c[1]), "+f"(c[2]), "+f"(c[3])
        : "r"(a[0]), "r"(a[1]), "r"(a[2]), "r"(a[3]), "r"(b[0]), "r"(b[1]));
}

__device__ __forceinline__ uint16_t bf16_bits(float f) {
    return __bfloat16_as_ushort(__float2bfloat16(f));
}
__device__ __forceinline__ float bf16_val(uint16_t u) {
    return __bfloat162float(__ushort_as_bfloat16(u));
}

// ===========================================================================
// Split-bf16 projection GEMM via mma.sync.
// out[n,d] = sum_k x[n,k]*w[k,d] + bias[d], written to [B,H,S,DH].
// CTA tile 128x128, 256 thr (8 warps, 2x4 of 64x32 warp tiles), KC=32.
// Smem: A (hi/lo) as [m][k], B (hi/lo) transposed to [n][k]; stride 34 u16
// so fragment k-pairs are single aligned 32-bit words.
// ===========================================================================
#define KC 32
#define STRD 34            // u16 stride (17 words)

__global__ void __launch_bounds__(256, 2) proj_mma_kernel(
    const float* __restrict__ x, const float* __restrict__ w,
    const float* __restrict__ bias, float* __restrict__ out)
{
    __shared__ __align__(16) uint16_t Ah[128 * STRD], Al[128 * STRD];
    __shared__ __align__(16) uint16_t Bh[128 * STRD], Bl[128 * STRD];
    uint32_t* Ah32 = reinterpret_cast<uint32_t*>(Ah);
    uint32_t* Al32 = reinterpret_cast<uint32_t*>(Al);
    uint32_t* Bh32 = reinterpret_cast<uint32_t*>(Bh);
    uint32_t* Bl32 = reinterpret_cast<uint32_t*>(Bl);

    const int tid  = threadIdx.x;
    const int wid  = tid >> 5, lane = tid & 31;
    const int g    = lane >> 2, tig = lane & 3;      // group / thread-in-group
    const int wm   = wid >> 2;                        // 0..1 -> m offset wm*64
    const int wn   = wid & 3;                         // 0..3 -> n offset wn*32
    const int row0 = blockIdx.y * 128;
    const int col0 = blockIdx.x * 128;

    float c[4][4][4];                                 // [mt][nt][frag]
    #pragma unroll
    for (int mt = 0; mt < 4; mt++)
        #pragma unroll
        for (int nt = 0; nt < 4; nt++)
            #pragma unroll
            for (int q = 0; q < 4; q++) c[mt][nt][q] = 0.0f;

    for (int kc = 0; kc < D_ / KC; kc++) {
        const int k0 = kc * KC;

        // --- stage A: x[row0+r][k0+c], split hi/lo, [m][k] layout -----------
        #pragma unroll
        for (int l = 0; l < 4; l++) {
            int f  = tid + l * 256;                   // 0..1023
            int r  = f >> 3, c4 = f & 7;
            float4 v = *reinterpret_cast<const float4*>(x + (row0 + r) * D_ + k0 + c4 * 4);
            uint16_t h0 = bf16_bits(v.x), h1 = bf16_bits(v.y);
            uint16_t h2 = bf16_bits(v.z), h3 = bf16_bits(v.w);
            uint16_t l0 = bf16_bits(v.x - bf16_val(h0));
            uint16_t l1 = bf16_bits(v.y - bf16_val(h1));
            uint16_t l2 = bf16_bits(v.z - bf16_val(h2));
            uint16_t l3 = bf16_bits(v.w - bf16_val(h3));
            int wbase = r * (STRD / 2) + c4 * 2;
            Ah32[wbase]     = (uint32_t)h1 << 16 | h0;
            Ah32[wbase + 1] = (uint32_t)h3 << 16 | h2;
            Al32[wbase]     = (uint32_t)l1 << 16 | l0;
            Al32[wbase + 1] = (uint32_t)l3 << 16 | l2;
        }
        // --- stage B: w[k0+k][col0+n] -> transpose to [n][k] ----------------
        #pragma unroll
        for (int l = 0; l < 4; l++) {
            int f  = tid + l * 256;
            int k  = f >> 5, c4 = f & 31;
            float4 v = *reinterpret_cast<const float4*>(w + (k0 + k) * D_ + col0 + c4 * 4);
            float vv[4] = {v.x, v.y, v.z, v.w};
            #pragma unroll
            for (int j = 0; j < 4; j++) {
                uint16_t hb = bf16_bits(vv[j]);
                uint16_t lb = bf16_bits(vv[j] - bf16_val(hb));
                int n = c4 * 4 + j;
                Bh[n * STRD + k] = hb;
                Bl[n * STRD + k] = lb;
            }
        }
        __syncthreads();

        // --- compute: 2 k-steps of 16 ---------------------------------------
        #pragma unroll
        for (int ks = 0; ks < 2; ks++) {
            const int kw = ks * 8;                    // k word offset
            uint32_t ah[4][4], al[4][4], bh[4][2], bl[4][2];
            #pragma unroll
            for (int mt = 0; mt < 4; mt++) {
                int m = wm * 64 + mt * 16;
                int b0 = (m + g) * (STRD / 2) + kw + tig;
                int b1 = (m + g + 8) * (STRD / 2) + kw + tig;
                ah[mt][0] = Ah32[b0];     ah[mt][1] = Ah32[b1];
                ah[mt][2] = Ah32[b0 + 4]; ah[mt][3] = Ah32[b1 + 4];
                al[mt][0] = Al32[b0];     al[mt][1] = Al32[b1];
                al[mt][2] = Al32[b0 + 4]; al[mt][3] = Al32[b1 + 4];
            }
            #pragma unroll
            for (int nt = 0; nt < 4; nt++) {
                int n = wn * 32 + nt * 8 + g;
                int b0 = n * (STRD / 2) + kw + tig;
                bh[nt][0] = Bh32[b0]; bh[nt][1] = Bh32[b0 + 4];
                bl[nt][0] = Bl32[b0]; bl[nt][1] = Bl32[b0 + 4];
            }
            #pragma unroll
            for (int mt = 0; mt < 4; mt++)
                #pragma unroll
                for (int nt = 0; nt < 4; nt++) {
                    mma16816(c[mt][nt], ah[mt], bh[nt]);   // hi*hi
                    mma16816(c[mt][nt], ah[mt], bl[nt]);   // hi*lo
                    mma16816(c[mt][nt], al[mt], bh[nt]);   // lo*hi
                }
        }
        __syncthreads();
    }

    // --- epilogue: bias + store to [B,H,S,DH] -------------------------------
    #pragma unroll
    for (int mt = 0; mt < 4; mt++) {
        #pragma unroll
        for (int nt = 0; nt < 4; nt++) {
            int gr = row0 + wm * 64 + mt * 16 + g;
            int gc = col0 + wn * 32 + nt * 8 + 2 * tig;
            float bx = bias[gc], by = bias[gc + 1];
            int h = gc >> 6, dh = gc & 63;
            // row gr
            {
                int b = gr >> 11, s = gr & (S_ - 1);
                float2 v = {c[mt][nt][0] + bx, c[mt][nt][1] + by};
                *reinterpret_cast<float2*>(out + (((b * H_ + h) * S_) + s) * DH_ + dh) = v;
            }
            // row gr+8
            {
                int gr2 = gr + 8;
                int b = gr2 >> 11, s = gr2 & (S_ - 1);
                float2 v = {c[mt][nt][2] + bx, c[mt][nt][3] + by};
                *reinterpret_cast<float2*>(out + (((b * H_ + h) * S_) + s) * DH_ + dh) = v;
            }
        }
    }
}

// ---------------------------------------------------------------------------
// Flash attention (fp32, online softmax) — unchanged SIMT baseline.
// ---------------------------------------------------------------------------
__global__ __launch_bounds__(256) void attn_kernel(
    const float* __restrict__ gq, const float* __restrict__ gk,
    const float* __restrict__ gv, float* __restrict__ out)
{
    extern __shared__ float smf[];
    float* Qs = smf;                 // [64][64]
    float* KP = smf + 64 * 64;       // [64][65]
    float* Vs = KP + 64 * 65;        // [64][64]

    const int tid = threadIdx.x;
    const int tx = tid & 15, ty = tid >> 4;
    const int bh = blockIdx.y;
    const int q0 = blockIdx.x * 64;

    const int base_q = (bh * S_ + q0) * DH_;
    #pragma unroll
    for (int l = 0; l < 16; l++) {
        int idx = tid + l * 256;
        Qs[idx] = gq[base_q + idx];
    }

    float m[4], lsum[4], acc[4][4];
    #pragma unroll
    for (int i = 0; i < 4; i++) {
        m[i] = -1e30f; lsum[i] = 0.0f;
        #pragma unroll
        for (int c = 0; c < 4; c++) acc[i][c] = 0.0f;
    }

    for (int kt = 0; kt < S_ / 64; kt++) {
        const int base_k = (bh * S_ + kt * 64) * DH_;
        #pragma unroll
        for (int l = 0; l < 16; l++) {
            int idx = tid + l * 256;
            int r = idx >> 6, c = idx & 63;
            KP[r * 65 + c] = gk[base_k + idx];
            Vs[idx]        = gv[base_k + idx];
        }
        __syncthreads();

        float s[4][4];
        #pragma unroll
        for (int i = 0; i < 4; i++)
            #pragma unroll
            for (int j = 0; j < 4; j++) s[i][j] = 0.0f;

        #pragma unroll 8
        for (int d = 0; d < 64; d++) {
            float a[4], b[4];
            #pragma unroll
            for (int i = 0; i < 4; i++) a[i] = Qs[(ty * 4 + i) * 64 + d];
            #pragma unroll
            for (int j = 0; j < 4; j++) b[j] = KP[(tx + 16 * j) * 65 + d];
            #pragma unroll
            for (int i = 0; i < 4; i++)
                #pragma unroll
                for (int j = 0; j < 4; j++)
                    s[i][j] = fmaf(a[i], b[j], s[i][j]);
        }

        #pragma unroll
        for (int i = 0; i < 4; i++) {
            float mx = s[i][0];
            #pragma unroll
            for (int j = 1; j < 4; j++) mx = fmaxf(mx, s[i][j]);
            mx *= 0.125f;
            #pragma unroll
            for (int off = 1; off < 16; off <<= 1)
                mx = fmaxf(mx, __shfl_xor_sync(0xffffffffu, mx, off));
            float mnew  = fmaxf(m[i], mx);
            float alpha = __expf(m[i] - mnew);
            float rs = 0.0f;
            #pragma unroll
            for (int j = 0; j < 4; j++) {
                s[i][j] = __expf(fmaf(s[i][j], 0.125f, -mnew));
                rs += s[i][j];
            }
            #pragma unroll
            for (int off = 1; off < 16; off <<= 1)
                rs += __shfl_xor_sync(0xffffffffu, rs, off);
            lsum[i] = lsum[i] * alpha + rs;
            m[i] = mnew;
            #pragma unroll
            for (int c = 0; c < 4; c++) acc[i][c] *= alpha;
        }

        __syncthreads();
        #pragma unroll
        for (int i = 0; i < 4; i++)
            #pragma unroll
            for (int j = 0; j < 4; j++)
                KP[(ty * 4 + i) * 65 + tx + 16 * j] = s[i][j];
        __syncthreads();

        #pragma unroll 8
        for (int j = 0; j < 64; j++) {
            float p[4], v[4];
            #pragma unroll
            for (int i = 0; i < 4; i++) p[i] = KP[(ty * 4 + i) * 65 + j];
            #pragma unroll
            for (int c = 0; c < 4; c++) v[c] = Vs[j * 64 + tx + 16 * c];
            #pragma unroll
            for (int i = 0; i < 4; i++)
                #pragma unroll
                for (int c = 0; c < 4; c++)
                    acc[i][c] = fmaf(p[i], v[c], acc[i][c]);
        }
        __syncthreads();
    }

    const int b_ = bh >> 4, h = bh & 15;
    #pragma unroll
    for (int i = 0; i < 4; i++) {
        int srow = q0 + ty * 4 + i;
        float inv = 1.0f / lsum[i];
        float* dst = out + (b_ * S_ + srow) * D_ + h * DH_;
        #pragma unroll
        for (int c = 0; c < 4; c++)
            dst[tx + 16 * c] = acc[i][c] * inv;
    }
}

// ---------------------------------------------------------------------------
extern "C" void kernel_launch(void* const* d_in, const int* in_sizes, int n_in,
                              void* d_out, int out_size)
{
    const float* vq = (const float*)d_in[0];
    const float* vk = (const float*)d_in[1];
    const float* vv = (const float*)d_in[2];
    const float* wq = (const float*)d_in[3];
    const float* bq = (const float*)d_in[4];
    const float* wk = (const float*)d_in[5];
    const float* bk = (const float*)d_in[6];
    const float* wv = (const float*)d_in[7];
    const float* bv = (const float*)d_in[8];
    float* out = (float*)d_out;

    void *pq, *pk, *pv;
    cudaGetSymbolAddress(&pq, g_q);
    cudaGetSymbolAddress(&pk, g_k);
    cudaGetSymbolAddress(&pv, g_v);

    dim3 grid_p(D_ / 128, NROW / 128);   // (8, 32)
    proj_mma_kernel<<<grid_p, 256>>>(vq, wq, bq, (float*)pq);
    proj_mma_kernel<<<grid_p, 256>>>(vk, wk, bk, (float*)pk);
    proj_mma_kernel<<<grid_p, 256>>>(vv, wv, bv, (float*)pv);

    const int smem_attn = (64 * 64 + 64 * 65 + 64 * 64) * 4;   // 49408
    cudaFuncSetAttribute(attn_kernel,
                         cudaFuncAttributeMaxDynamicSharedMemorySize, smem_attn);
    dim3 grid_a(S_ / 64, B_ * H_);       // (32, 32)
    attn_kernel<<<grid_a, 256, smem_attn>>>((const float*)pq, (const float*)pk,
                                            (const float*)pv, out);
}

// round 6
// speedup vs baseline: 2.0603x; 1.6085x over previous
#include <cuda_runtime.h>
#include <cuda_bf16.h>
#include <cstdint>

#define B_ 2
#define S_ 2048
#define D_ 1024
#define H_ 16
#define DH_ 64
#define NROW (B_ * S_)          // 4096
#define NELEM (B_ * H_ * S_ * DH_)

// Projected Q/K/V as split bf16 (hi + lo), [B,H,S,DH] layout
__device__ __nv_bfloat16 g_qh[NELEM], g_ql[NELEM];
__device__ __nv_bfloat16 g_kh[NELEM], g_kl[NELEM];
__device__ __nv_bfloat16 g_vh[NELEM], g_vl[NELEM];

// ---------------------------------------------------------------------------
// Warp-level bf16 MMA: D[16x8] += A[16x16] * B[16x8], fp32 accum.
// ---------------------------------------------------------------------------
__device__ __forceinline__ void mma16816(float* c, const uint32_t* a, const uint32_t* b) {
    asm volatile(
        "mma.sync.aligned.m16n8k16.row.col.f32.bf16.bf16.f32 "
        "{%0,%1,%2,%3}, {%4,%5,%6,%7}, {%8,%9}, {%0,%1,%2,%3};"
        : "+f"(c[0]), "+f"(c[1]), "+f"(c[2]), "+f"(c[3])
        : "r"(a[0]), "r"(a[1]), "r"(a[2]), "r"(a[3]), "r"(b[0]), "r"(b[1]));
}

__device__ __forceinline__ uint16_t bf16_bits(float f) {
    return __bfloat16_as_ushort(__float2bfloat16(f));
}
__device__ __forceinline__ float bf16_val(uint16_t u) {
    return __bfloat162float(__ushort_as_bfloat16(u));
}
__device__ __forceinline__ uint32_t pack_bf16x2(float lo, float hi) {
    return (uint32_t)bf16_bits(lo) | ((uint32_t)bf16_bits(hi) << 16);
}

// ===========================================================================
// Split-bf16 projection GEMM via mma.sync; emits bf16 hi/lo to [B,H,S,DH].
// CTA tile 128x128, 8 warps (2x4 of 64x32), KC=32.
// ===========================================================================
#define KC 32
#define STRD 34            // u16 stride (17 words)

__global__ void __launch_bounds__(256, 2) proj_mma_kernel(
    const float* __restrict__ x, const float* __restrict__ w,
    const float* __restrict__ bias,
    __nv_bfloat16* __restrict__ outh, __nv_bfloat16* __restrict__ outl)
{
    __shared__ __align__(16) uint16_t Ah[128 * STRD], Al[128 * STRD];
    __shared__ __align__(16) uint16_t Bh[128 * STRD], Bl[128 * STRD];
    uint32_t* Ah32 = reinterpret_cast<uint32_t*>(Ah);
    uint32_t* Al32 = reinterpret_cast<uint32_t*>(Al);
    uint32_t* Bh32 = reinterpret_cast<uint32_t*>(Bh);
    uint32_t* Bl32 = reinterpret_cast<uint32_t*>(Bl);

    const int tid  = threadIdx.x;
    const int wid  = tid >> 5, lane = tid & 31;
    const int g    = lane >> 2, tig = lane & 3;
    const int wm   = wid >> 2;
    const int wn   = wid & 3;
    const int row0 = blockIdx.y * 128;
    const int col0 = blockIdx.x * 128;

    float c[4][4][4];
    #pragma unroll
    for (int mt = 0; mt < 4; mt++)
        #pragma unroll
        for (int nt = 0; nt < 4; nt++)
            #pragma unroll
            for (int q = 0; q < 4; q++) c[mt][nt][q] = 0.0f;

    for (int kc = 0; kc < D_ / KC; kc++) {
        const int k0 = kc * KC;

        #pragma unroll
        for (int l = 0; l < 4; l++) {
            int f  = tid + l * 256;
            int r  = f >> 3, c4 = f & 7;
            float4 v = *reinterpret_cast<const float4*>(x + (row0 + r) * D_ + k0 + c4 * 4);
            uint16_t h0 = bf16_bits(v.x), h1 = bf16_bits(v.y);
            uint16_t h2 = bf16_bits(v.z), h3 = bf16_bits(v.w);
            uint16_t l0 = bf16_bits(v.x - bf16_val(h0));
            uint16_t l1 = bf16_bits(v.y - bf16_val(h1));
            uint16_t l2 = bf16_bits(v.z - bf16_val(h2));
            uint16_t l3 = bf16_bits(v.w - bf16_val(h3));
            int wbase = r * (STRD / 2) + c4 * 2;
            Ah32[wbase]     = (uint32_t)h1 << 16 | h0;
            Ah32[wbase + 1] = (uint32_t)h3 << 16 | h2;
            Al32[wbase]     = (uint32_t)l1 << 16 | l0;
            Al32[wbase + 1] = (uint32_t)l3 << 16 | l2;
        }
        #pragma unroll
        for (int l = 0; l < 4; l++) {
            int f  = tid + l * 256;
            int k  = f >> 5, c4 = f & 31;
            float4 v = *reinterpret_cast<const float4*>(w + (k0 + k) * D_ + col0 + c4 * 4);
            float vv[4] = {v.x, v.y, v.z, v.w};
            #pragma unroll
            for (int j = 0; j < 4; j++) {
                uint16_t hb = bf16_bits(vv[j]);
                uint16_t lb = bf16_bits(vv[j] - bf16_val(hb));
                int n = c4 * 4 + j;
                Bh[n * STRD + k] = hb;
                Bl[n * STRD + k] = lb;
            }
        }
        __syncthreads();

        #pragma unroll
        for (int ks = 0; ks < 2; ks++) {
            const int kw = ks * 8;
            uint32_t ah[4][4], al[4][4], bh[4][2], bl[4][2];
            #pragma unroll
            for (int mt = 0; mt < 4; mt++) {
                int m = wm * 64 + mt * 16;
                int b0 = (m + g) * (STRD / 2) + kw + tig;
                int b1 = (m + g + 8) * (STRD / 2) + kw + tig;
                ah[mt][0] = Ah32[b0];     ah[mt][1] = Ah32[b1];
                ah[mt][2] = Ah32[b0 + 4]; ah[mt][3] = Ah32[b1 + 4];
                al[mt][0] = Al32[b0];     al[mt][1] = Al32[b1];
                al[mt][2] = Al32[b0 + 4]; al[mt][3] = Al32[b1 + 4];
            }
            #pragma unroll
            for (int nt = 0; nt < 4; nt++) {
                int n = wn * 32 + nt * 8 + g;
                int b0 = n * (STRD / 2) + kw + tig;
                bh[nt][0] = Bh32[b0]; bh[nt][1] = Bh32[b0 + 4];
                bl[nt][0] = Bl32[b0]; bl[nt][1] = Bl32[b0 + 4];
            }
            #pragma unroll
            for (int mt = 0; mt < 4; mt++)
                #pragma unroll
                for (int nt = 0; nt < 4; nt++) {
                    mma16816(c[mt][nt], ah[mt], bh[nt]);
                    mma16816(c[mt][nt], ah[mt], bl[nt]);
                    mma16816(c[mt][nt], al[mt], bh[nt]);
                }
        }
        __syncthreads();
    }

    // epilogue: bias, split hi/lo, store bf16x2 to [B,H,S,DH]
    #pragma unroll
    for (int mt = 0; mt < 4; mt++) {
        #pragma unroll
        for (int nt = 0; nt < 4; nt++) {
            int gr = row0 + wm * 64 + mt * 16 + g;
            int gc = col0 + wn * 32 + nt * 8 + 2 * tig;
            float bx = bias[gc], by = bias[gc + 1];
            int h = gc >> 6, dh = gc & 63;
            #pragma unroll
            for (int half = 0; half < 2; half++) {
                int r = gr + half * 8;
                int b = r >> 11, s = r & (S_ - 1);
                float v0 = c[mt][nt][half * 2 + 0] + bx;
                float v1 = c[mt][nt][half * 2 + 1] + by;
                uint16_t h0 = bf16_bits(v0), h1 = bf16_bits(v1);
                uint16_t l0 = bf16_bits(v0 - bf16_val(h0));
                uint16_t l1 = bf16_bits(v1 - bf16_val(h1));
                int idx = (((b * H_ + h) * S_) + s) * DH_ + dh;
                *reinterpret_cast<uint32_t*>(outh + idx) = (uint32_t)h1 << 16 | h0;
                *reinterpret_cast<uint32_t*>(outl + idx) = (uint32_t)l1 << 16 | l0;
            }
        }
    }
}

// ===========================================================================
// Flash attention on split-bf16 mma.sync.
// CTA: one (b,h) x 128 query rows. 8 warps x 16 rows. Bc = 64 kv per iter.
// Smem stride 36 u32 => fragment loads hit banks (4g+tig): conflict-free.
// P (softmax probs) repacks from QK C-fragments into PV A-fragments in regs.
// ===========================================================================
#define ATS 36                               // u32 row stride
#define OFF_QH 0
#define OFF_QL (128 * ATS)                   // 4608
#define OFF_KH (2 * 128 * ATS)               // 9216
#define OFF_KL (OFF_KH + 64 * ATS)
#define OFF_VH (OFF_KL + 64 * ATS)
#define OFF_VL (OFF_VH + 64 * ATS)
#define ATT_SMEM_U32 (OFF_VL + 64 * ATS)     // 18432 u32 = 73728 B

__global__ void __launch_bounds__(256) attn_mma_kernel(
    const __nv_bfloat16* __restrict__ qh, const __nv_bfloat16* __restrict__ ql,
    const __nv_bfloat16* __restrict__ kh, const __nv_bfloat16* __restrict__ kl,
    const __nv_bfloat16* __restrict__ vh, const __nv_bfloat16* __restrict__ vl,
    float* __restrict__ out)
{
    extern __shared__ uint32_t sm32[];
    uint32_t* sQh = sm32 + OFF_QH;
    uint32_t* sQl = sm32 + OFF_QL;
    uint32_t* sKh = sm32 + OFF_KH;
    uint32_t* sKl = sm32 + OFF_KL;
    uint32_t* sVh = sm32 + OFF_VH;           // transposed [dh][kv]
    uint32_t* sVl = sm32 + OFF_VL;

    const int tid  = threadIdx.x;
    const int wid  = tid >> 5, lane = tid & 31;
    const int g    = lane >> 2, tig = lane & 3;
    const int bh   = blockIdx.y;             // b*H + h
    const int q0   = blockIdx.x * 128;

    // ---- stage Q (128 x 64 hi/lo) ----
    {
        const uint32_t* gqh = reinterpret_cast<const uint32_t*>(qh + (bh * S_ + q0) * DH_);
        const uint32_t* gql = reinterpret_cast<const uint32_t*>(ql + (bh * S_ + q0) * DH_);
        #pragma unroll
        for (int l = 0; l < 16; l++) {
            int idx = tid + l * 256;         // 0..4095
            int r = idx >> 5, cw = idx & 31;
            sQh[r * ATS + cw] = gqh[idx];
            sQl[r * ATS + cw] = gql[idx];
        }
    }

    float m0 = -1e30f, m1 = -1e30f, l0 = 0.0f, l1 = 0.0f;
    float acc[8][4];
    #pragma unroll
    for (int nt = 0; nt < 8; nt++)
        #pragma unroll
        for (int q = 0; q < 4; q++) acc[nt][q] = 0.0f;

    const int mrow = wid * 16;               // warp's first q row in tile

    for (int kt = 0; kt < S_ / 64; kt++) {
        // ---- stage K (copy) and V (transpose) ----
        {
            const int base = (bh * S_ + kt * 64) * DH_;
            const uint32_t* gkh = reinterpret_cast<const uint32_t*>(kh + base);
            const uint32_t* gkl = reinterpret_cast<const uint32_t*>(kl + base);
            const uint32_t* gvh = reinterpret_cast<const uint32_t*>(vh + base);
            const uint32_t* gvl = reinterpret_cast<const uint32_t*>(vl + base);
            uint16_t* tVh = reinterpret_cast<uint16_t*>(sVh);
            uint16_t* tVl = reinterpret_cast<uint16_t*>(sVl);
            #pragma unroll
            for (int l = 0; l < 8; l++) {
                int idx = tid + l * 256;     // 0..2047
                int r = idx >> 5, cw = idx & 31;
                sKh[r * ATS + cw] = gkh[idx];
                sKl[r * ATS + cw] = gkl[idx];
                uint32_t uh = gvh[idx], ul = gvl[idx];
                tVh[(2 * cw)     * (2 * ATS) + r] = (uint16_t)(uh & 0xffff);
                tVh[(2 * cw + 1) * (2 * ATS) + r] = (uint16_t)(uh >> 16);
                tVl[(2 * cw)     * (2 * ATS) + r] = (uint16_t)(ul & 0xffff);
                tVl[(2 * cw + 1) * (2 * ATS) + r] = (uint16_t)(ul >> 16);
            }
        }
        __syncthreads();

        // ---- QK^T: scores 16x64 per warp ----
        float sc[8][4];
        #pragma unroll
        for (int nt = 0; nt < 8; nt++)
            #pragma unroll
            for (int q = 0; q < 4; q++) sc[nt][q] = 0.0f;

        #pragma unroll
        for (int ks = 0; ks < 4; ks++) {
            uint32_t ah[4], al[4];
            int a0 = (mrow + g) * ATS + ks * 8 + tig;
            int a1 = (mrow + g + 8) * ATS + ks * 8 + tig;
            ah[0] = sQh[a0]; ah[1] = sQh[a1]; ah[2] = sQh[a0 + 4]; ah[3] = sQh[a1 + 4];
            al[0] = sQl[a0]; al[1] = sQl[a1]; al[2] = sQl[a0 + 4]; al[3] = sQl[a1 + 4];
            #pragma unroll
            for (int nt = 0; nt < 8; nt++) {
                int bb = (nt * 8 + g) * ATS + ks * 8 + tig;
                uint32_t bhf[2] = {sKh[bb], sKh[bb + 4]};
                uint32_t blf[2] = {sKl[bb], sKl[bb + 4]};
                mma16816(sc[nt], ah, bhf);
                mma16816(sc[nt], ah, blf);
                mma16816(sc[nt], al, bhf);
            }
        }

        // ---- online softmax (warp-local; rows g and g+8) ----
        {
            float mx0 = -1e30f, mx1 = -1e30f;
            #pragma unroll
            for (int nt = 0; nt < 8; nt++) {
                mx0 = fmaxf(mx0, fmaxf(sc[nt][0], sc[nt][1]));
                mx1 = fmaxf(mx1, fmaxf(sc[nt][2], sc[nt][3]));
            }
            mx0 *= 0.125f; mx1 *= 0.125f;
            #pragma unroll
            for (int off = 1; off < 4; off <<= 1) {
                mx0 = fmaxf(mx0, __shfl_xor_sync(0xffffffffu, mx0, off));
                mx1 = fmaxf(mx1, __shfl_xor_sync(0xffffffffu, mx1, off));
            }
            float mn0 = fmaxf(m0, mx0), mn1 = fmaxf(m1, mx1);
            float al0 = __expf(m0 - mn0), al1 = __expf(m1 - mn1);
            float s0 = 0.0f, s1 = 0.0f;
            #pragma unroll
            for (int nt = 0; nt < 8; nt++) {
                sc[nt][0] = __expf(fmaf(sc[nt][0], 0.125f, -mn0));
                sc[nt][1] = __expf(fmaf(sc[nt][1], 0.125f, -mn0));
                sc[nt][2] = __expf(fmaf(sc[nt][2], 0.125f, -mn1));
                sc[nt][3] = __expf(fmaf(sc[nt][3], 0.125f, -mn1));
                s0 += sc[nt][0] + sc[nt][1];
                s1 += sc[nt][2] + sc[nt][3];
            }
            #pragma unroll
            for (int off = 1; off < 4; off <<= 1) {
                s0 += __shfl_xor_sync(0xffffffffu, s0, off);
                s1 += __shfl_xor_sync(0xffffffffu, s1, off);
            }
            l0 = l0 * al0 + s0; l1 = l1 * al1 + s1;
            m0 = mn0; m1 = mn1;
            #pragma unroll
            for (int nt = 0; nt < 8; nt++) {
                acc[nt][0] *= al0; acc[nt][1] *= al0;
                acc[nt][2] *= al1; acc[nt][3] *= al1;
            }
        }

        // ---- P @ V: A-fragments repacked from score C-fragments ----
        #pragma unroll
        for (int kk = 0; kk < 4; kk++) {
            float p00 = sc[2*kk][0],   p01 = sc[2*kk][1];
            float p10 = sc[2*kk][2],   p11 = sc[2*kk][3];
            float r00 = sc[2*kk+1][0], r01 = sc[2*kk+1][1];
            float r10 = sc[2*kk+1][2], r11 = sc[2*kk+1][3];
            uint32_t pah[4], pal[4];
            // hi parts
            uint16_t h00 = bf16_bits(p00), h01 = bf16_bits(p01);
            uint16_t h10 = bf16_bits(p10), h11 = bf16_bits(p11);
            uint16_t i00 = bf16_bits(r00), i01 = bf16_bits(r01);
            uint16_t i10 = bf16_bits(r10), i11 = bf16_bits(r11);
            pah[0] = (uint32_t)h01 << 16 | h00;
            pah[1] = (uint32_t)h11 << 16 | h10;
            pah[2] = (uint32_t)i01 << 16 | i00;
            pah[3] = (uint32_t)i11 << 16 | i10;
            // lo parts
            pal[0] = pack_bf16x2(p00 - bf16_val(h00), p01 - bf16_val(h01));
            pal[1] = pack_bf16x2(p10 - bf16_val(h10), p11 - bf16_val(h11));
            pal[2] = pack_bf16x2(r00 - bf16_val(i00), r01 - bf16_val(i01));
            pal[3] = pack_bf16x2(r10 - bf16_val(i10), r11 - bf16_val(i11));
            #pragma unroll
            for (int nt = 0; nt < 8; nt++) {
                int bb = (nt * 8 + g) * ATS + kk * 8 + tig;
                uint32_t vhf[2] = {sVh[bb], sVh[bb + 4]};
                uint32_t vlf[2] = {sVl[bb], sVl[bb + 4]};
                mma16816(acc[nt], pah, vhf);
                mma16816(acc[nt], pah, vlf);
                mma16816(acc[nt], pal, vhf);
            }
        }
        __syncthreads();   // done with K/V smem before next stage
    }

    // ---- epilogue: normalize, store to [B,S,D] ----
    {
        const int b = bh >> 4, h = bh & 15;
        float inv0 = 1.0f / l0, inv1 = 1.0f / l1;
        int r0 = q0 + mrow + g, r1 = r0 + 8;
        #pragma unroll
        for (int nt = 0; nt < 8; nt++) {
            int col = nt * 8 + 2 * tig;
            float2 o0 = {acc[nt][0] * inv0, acc[nt][1] * inv0};
            float2 o1 = {acc[nt][2] * inv1, acc[nt][3] * inv1};
            *reinterpret_cast<float2*>(out + (b * S_ + r0) * D_ + h * DH_ + col) = o0;
            *reinterpret_cast<float2*>(out + (b * S_ + r1) * D_ + h * DH_ + col) = o1;
        }
    }
}

// ---------------------------------------------------------------------------
extern "C" void kernel_launch(void* const* d_in, const int* in_sizes, int n_in,
                              void* d_out, int out_size)
{
    const float* vq = (const float*)d_in[0];
    const float* vk = (const float*)d_in[1];
    const float* vv = (const float*)d_in[2];
    const float* wq = (const float*)d_in[3];
    const float* bq = (const float*)d_in[4];
    const float* wk = (const float*)d_in[5];
    const float* bk = (const float*)d_in[6];
    const float* wv = (const float*)d_in[7];
    const float* bv = (const float*)d_in[8];
    float* out = (float*)d_out;

    void *pqh, *pql, *pkh, *pkl, *pvh, *pvl;
    cudaGetSymbolAddress(&pqh, g_qh); cudaGetSymbolAddress(&pql, g_ql);
    cudaGetSymbolAddress(&pkh, g_kh); cudaGetSymbolAddress(&pkl, g_kl);
    cudaGetSymbolAddress(&pvh, g_vh); cudaGetSymbolAddress(&pvl, g_vl);

    dim3 grid_p(D_ / 128, NROW / 128);   // (8, 32)
    proj_mma_kernel<<<grid_p, 256>>>(vq, wq, bq, (__nv_bfloat16*)pqh, (__nv_bfloat16*)pql);
    proj_mma_kernel<<<grid_p, 256>>>(vk, wk, bk, (__nv_bfloat16*)pkh, (__nv_bfloat16*)pkl);
    proj_mma_kernel<<<grid_p, 256>>>(vv, wv, bv, (__nv_bfloat16*)pvh, (__nv_bfloat16*)pvl);

    const int smem_attn = ATT_SMEM_U32 * 4;   // 73728
    cudaFuncSetAttribute(attn_mma_kernel,
                         cudaFuncAttributeMaxDynamicSharedMemorySize, smem_attn);
    dim3 grid_a(S_ / 128, B_ * H_);           // (16, 32)
    attn_mma_kernel<<<grid_a, 256, smem_attn>>>(
        (const __nv_bfloat16*)pqh, (const __nv_bfloat16*)pql,
        (const __nv_bfloat16*)pkh, (const __nv_bfloat16*)pkl,
        (const __nv_bfloat16*)pvh, (const __nv_bfloat16*)pvl, out);
}

// round 7
// speedup vs baseline: 2.8580x; 1.3872x over previous
#include <cuda_runtime.h>
#include <cuda_bf16.h>
#include <cstdint>

#define B_ 2
#define S_ 2048
#define D_ 1024
#define H_ 16
#define DH_ 64
#define NROW (B_ * S_)          // 4096
#define NELEM (B_ * H_ * S_ * DH_)

// Pre-split inputs/weights and projected outputs (hi+lo bf16).
// g_ph/g_pl: z=0 Q [B,H,S,DH], z=1 K [B,H,S,DH], z=2 V TRANSPOSED [B,H,DH,S]
__device__ __nv_bfloat16 g_xh[3 * NROW * D_], g_xl[3 * NROW * D_];
__device__ __nv_bfloat16 g_wh[3 * D_ * D_],   g_wl[3 * D_ * D_];
__device__ __nv_bfloat16 g_ph[3 * NELEM],     g_pl[3 * NELEM];

// ---------------------------------------------------------------------------
// helpers
// ---------------------------------------------------------------------------
__device__ __forceinline__ void mma16816(float* c, const uint32_t* a, const uint32_t* b) {
    asm volatile(
        "mma.sync.aligned.m16n8k16.row.col.f32.bf16.bf16.f32 "
        "{%0,%1,%2,%3}, {%4,%5,%6,%7}, {%8,%9}, {%0,%1,%2,%3};"
        : "+f"(c[0]), "+f"(c[1]), "+f"(c[2]), "+f"(c[3])
        : "r"(a[0]), "r"(a[1]), "r"(a[2]), "r"(a[3]), "r"(b[0]), "r"(b[1]));
}
__device__ __forceinline__ uint16_t bf16_bits(float f) {
    return __bfloat16_as_ushort(__float2bfloat16(f));
}
__device__ __forceinline__ float bf16_val(uint16_t u) {
    return __bfloat162float(__ushort_as_bfloat16(u));
}
__device__ __forceinline__ uint32_t pack_bf16x2(float lo, float hi) {
    return (uint32_t)bf16_bits(lo) | ((uint32_t)bf16_bits(hi) << 16);
}
__device__ __forceinline__ uint32_t smem_u32(const void* p) {
    uint32_t a;
    asm("{ .reg .u64 t; cvta.to.shared.u64 t, %1; cvt.u32.u64 %0, t; }"
        : "=r"(a) : "l"(p));
    return a;
}
#define CP16(dst_bytes, srcp) \
    asm volatile("cp.async.cg.shared.global [%0], [%1], 16;" \
                 :: "r"(dst_bytes), "l"(__cvta_generic_to_global((const void*)(srcp))) : "memory")
#define CP_COMMIT() asm volatile("cp.async.commit_group;" ::: "memory")
#define CP_WAIT1()  asm volatile("cp.async.wait_group 1;" ::: "memory")
#define CP_WAIT0()  asm volatile("cp.async.wait_group 0;" ::: "memory")

// ===========================================================================
// Pre-split kernels
// ===========================================================================
__global__ void __launch_bounds__(256) xsplit_kernel(
    const float* __restrict__ xq, const float* __restrict__ xk, const float* __restrict__ xv)
{
    const int z = blockIdx.y;
    const float* x = (z == 0) ? xq : (z == 1) ? xk : xv;
    const int base = z * NROW * D_;
    int i4 = blockIdx.x * 256 + threadIdx.x;          // float4 index, 1M total
    float4 v = reinterpret_cast<const float4*>(x)[i4];
    uint16_t hx = bf16_bits(v.x), hy = bf16_bits(v.y);
    uint16_t hz = bf16_bits(v.z), hw = bf16_bits(v.w);
    uint32_t* oh = reinterpret_cast<uint32_t*>(g_xh + base);
    uint32_t* ol = reinterpret_cast<uint32_t*>(g_xl + base);
    oh[2 * i4]     = (uint32_t)hy << 16 | hx;
    oh[2 * i4 + 1] = (uint32_t)hw << 16 | hz;
    ol[2 * i4]     = pack_bf16x2(v.x - bf16_val(hx), v.y - bf16_val(hy));
    ol[2 * i4 + 1] = pack_bf16x2(v.z - bf16_val(hz), v.w - bf16_val(hw));
}

// transpose-split weights: g_w*[z][n][k] = split(w[k][n])
__global__ void __launch_bounds__(256) wsplit_kernel(
    const float* __restrict__ wq, const float* __restrict__ wk, const float* __restrict__ wv)
{
    __shared__ float t[32][33];
    const int z = blockIdx.z;
    const float* w = (z == 0) ? wq : (z == 1) ? wk : wv;
    const int base = z * D_ * D_;
    const int n0 = blockIdx.x * 32, k0 = blockIdx.y * 32;
    const int tx = threadIdx.x & 31, ty = threadIdx.x >> 5;   // 32 x 8
    #pragma unroll
    for (int j = 0; j < 32; j += 8)
        t[ty + j][tx] = w[(k0 + ty + j) * D_ + n0 + tx];
    __syncthreads();
    #pragma unroll
    for (int j = 0; j < 32; j += 8) {
        float v = t[tx][ty + j];                               // w[k0+tx][n0+ty+j]
        uint16_t hb = bf16_bits(v);
        uint16_t lb = bf16_bits(v - bf16_val(hb));
        int idx = base + (n0 + ty + j) * D_ + k0 + tx;
        g_wh[idx] = __ushort_as_bfloat16(hb);
        g_wl[idx] = __ushort_as_bfloat16(lb);
    }
}

// ===========================================================================
// Projection GEMM v2: pre-split bf16 inputs, cp.async double-buffered.
// CTA 128x128, 8 warps (2x4 of 64x32), KC=32, smem row stride 20 u32
// (frag-load banks 20g+tig mod 32 => all 32 lanes distinct).
// grid.z selects projection; z==2 (V) stores transposed [B,H,DH,S].
// ===========================================================================
#define KC 32
#define PST 20                     // u32 row stride
#define PARR 2560                  // u32 per array (128*20)
#define PSTG (4 * PARR)            // u32 per stage
#define PROJ_SMEM_BYTES (2 * PSTG * 4)   // 81920

__global__ void __launch_bounds__(256, 2) proj_mma_kernel(
    const float* __restrict__ bq, const float* __restrict__ bk, const float* __restrict__ bv)
{
    extern __shared__ uint32_t ps[];
    const uint32_t sbase = smem_u32(ps);

    const int z = blockIdx.z;
    const __nv_bfloat16* xh = g_xh + z * NROW * D_;
    const __nv_bfloat16* xl = g_xl + z * NROW * D_;
    const __nv_bfloat16* wh = g_wh + z * D_ * D_;
    const __nv_bfloat16* wl = g_wl + z * D_ * D_;
    __nv_bfloat16* outh = g_ph + z * NELEM;
    __nv_bfloat16* outl = g_pl + z * NELEM;
    const float* bias = (z == 0) ? bq : (z == 1) ? bk : bv;
    const bool vmode = (z == 2);

    const int tid  = threadIdx.x;
    const int wid  = tid >> 5, lane = tid & 31;
    const int g    = lane >> 2, tig = lane & 3;
    const int wm   = wid >> 2, wn = wid & 3;
    const int row0 = blockIdx.y * 128;
    const int col0 = blockIdx.x * 128;

    auto stage = [&](int kc, int st) {
        const int k0 = kc * KC;
        const uint32_t so = sbase + st * (PSTG * 4);
        #pragma unroll
        for (int l = 0; l < 2; l++) {
            int ci = tid + l * 256;                 // 0..511
            int r = ci >> 2, cc = ci & 3;
            uint32_t d = so + (r * PST + cc * 4) * 4;
            CP16(d + 0 * PARR * 4, xh + (row0 + r) * D_ + k0 + cc * 8);
            CP16(d + 1 * PARR * 4, xl + (row0 + r) * D_ + k0 + cc * 8);
            CP16(d + 2 * PARR * 4, wh + (col0 + r) * D_ + k0 + cc * 8);
            CP16(d + 3 * PARR * 4, wl + (col0 + r) * D_ + k0 + cc * 8);
        }
    };

    float c[4][4][4];
    #pragma unroll
    for (int mt = 0; mt < 4; mt++)
        #pragma unroll
        for (int nt = 0; nt < 4; nt++)
            #pragma unroll
            for (int q = 0; q < 4; q++) c[mt][nt][q] = 0.0f;

    stage(0, 0); CP_COMMIT();

    for (int kc = 0; kc < D_ / KC; kc++) {
        if (kc < D_ / KC - 1) { stage(kc + 1, (kc + 1) & 1); CP_COMMIT(); CP_WAIT1(); }
        else                  { CP_WAIT0(); }
        __syncthreads();

        uint32_t* Ah32 = ps + (kc & 1) * PSTG;
        uint32_t* Al32 = Ah32 + PARR;
        uint32_t* Bh32 = Ah32 + 2 * PARR;
        uint32_t* Bl32 = Ah32 + 3 * PARR;

        #pragma unroll
        for (int ks = 0; ks < 2; ks++) {
            const int kw = ks * 8;
            uint32_t ah[4][4], al[4][4], bhf[4][2], blf[4][2];
            #pragma unroll
            for (int mt = 0; mt < 4; mt++) {
                int m = wm * 64 + mt * 16;
                int b0 = (m + g) * PST + kw + tig;
                int b1 = (m + g + 8) * PST + kw + tig;
                ah[mt][0] = Ah32[b0];     ah[mt][1] = Ah32[b1];
                ah[mt][2] = Ah32[b0 + 4]; ah[mt][3] = Ah32[b1 + 4];
                al[mt][0] = Al32[b0];     al[mt][1] = Al32[b1];
                al[mt][2] = Al32[b0 + 4]; al[mt][3] = Al32[b1 + 4];
            }
            #pragma unroll
            for (int nt = 0; nt < 4; nt++) {
                int n = wn * 32 + nt * 8 + g;
                int b0 = n * PST + kw + tig;
                bhf[nt][0] = Bh32[b0]; bhf[nt][1] = Bh32[b0 + 4];
                blf[nt][0] = Bl32[b0]; blf[nt][1] = Bl32[b0 + 4];
            }
            #pragma unroll
            for (int mt = 0; mt < 4; mt++)
                #pragma unroll
                for (int nt = 0; nt < 4; nt++) {
                    mma16816(c[mt][nt], ah[mt], bhf[nt]);
                    mma16816(c[mt][nt], ah[mt], blf[nt]);
                    mma16816(c[mt][nt], al[mt], bhf[nt]);
                }
        }
        __syncthreads();
    }

    // epilogue: bias, split hi/lo, store
    #pragma unroll
    for (int mt = 0; mt < 4; mt++) {
        #pragma unroll
        for (int nt = 0; nt < 4; nt++) {
            int gr = row0 + wm * 64 + mt * 16 + g;
            int gc = col0 + wn * 32 + nt * 8 + 2 * tig;
            float bx = bias[gc], by = bias[gc + 1];
            int h = gc >> 6, dh = gc & 63;
            #pragma unroll
            for (int half = 0; half < 2; half++) {
                int r = gr + half * 8;
                int b = r >> 11, s = r & (S_ - 1);
                float v0 = c[mt][nt][half * 2 + 0] + bx;
                float v1 = c[mt][nt][half * 2 + 1] + by;
                uint16_t h0 = bf16_bits(v0), h1 = bf16_bits(v1);
                uint16_t l0 = bf16_bits(v0 - bf16_val(h0));
                uint16_t l1 = bf16_bits(v1 - bf16_val(h1));
                if (!vmode) {
                    int idx = (((b * H_ + h) * S_) + s) * DH_ + dh;
                    *reinterpret_cast<uint32_t*>(outh + idx) = (uint32_t)h1 << 16 | h0;
                    *reinterpret_cast<uint32_t*>(outl + idx) = (uint32_t)l1 << 16 | l0;
                } else {
                    int ib = (b * H_ + h) * DH_;
                    outh[(ib + dh) * S_ + s]     = __ushort_as_bfloat16(h0);
                    outh[(ib + dh + 1) * S_ + s] = __ushort_as_bfloat16(h1);
                    outl[(ib + dh) * S_ + s]     = __ushort_as_bfloat16(l0);
                    outl[(ib + dh + 1) * S_ + s] = __ushort_as_bfloat16(l1);
                }
            }
        }
    }
}

// ===========================================================================
// Flash attention: cp.async double-buffered K/V (V pre-transposed in gmem),
// split-bf16 mma.sync core unchanged from R5.
// ===========================================================================
#define ATS 36                               // u32 row stride
#define AQH 0
#define AQL (128 * ATS)                      // 4608
#define AKV (2 * 128 * ATS)                  // 9216
#define AKVARR (64 * ATS)                    // 2304 u32 per array
#define AKVS (4 * AKVARR)                    // 9216 u32 per stage
#define ATT_SMEM_BYTES ((AKV + 2 * AKVS) * 4)   // 110592

__global__ void __launch_bounds__(256) attn_mma_kernel(float* __restrict__ out)
{
    extern __shared__ uint32_t sm32[];
    const uint32_t sbase = smem_u32(sm32);

    const int tid  = threadIdx.x;
    const int wid  = tid >> 5, lane = tid & 31;
    const int g    = lane >> 2, tig = lane & 3;
    const int bh   = blockIdx.y;
    const int q0   = blockIdx.x * 128;

    const __nv_bfloat16* qh = g_ph;
    const __nv_bfloat16* ql = g_pl;
    const __nv_bfloat16* kh = g_ph + NELEM;
    const __nv_bfloat16* kl = g_pl + NELEM;
    const __nv_bfloat16* vh = g_ph + 2 * NELEM;   // [B,H,DH,S]
    const __nv_bfloat16* vl = g_pl + 2 * NELEM;

    auto stageKV = [&](int kt, int st) {
        const uint32_t so = sbase + (AKV + st * AKVS) * 4;
        const __nv_bfloat16* kbh = kh + (bh * S_ + kt * 64) * DH_;
        const __nv_bfloat16* kbl = kl + (bh * S_ + kt * 64) * DH_;
        const __nv_bfloat16* vbh = vh + bh * DH_ * S_ + kt * 64;
        const __nv_bfloat16* vbl = vl + bh * DH_ * S_ + kt * 64;
        #pragma unroll
        for (int l = 0; l < 2; l++) {
            int ci = tid + l * 256;                // 0..511
            int r = ci >> 3, cc = ci & 7;
            uint32_t d = so + (r * ATS + cc * 4) * 4;
            CP16(d + 0 * AKVARR * 4, kbh + r * DH_ + cc * 8);
            CP16(d + 1 * AKVARR * 4, kbl + r * DH_ + cc * 8);
            CP16(d + 2 * AKVARR * 4, vbh + r * S_ + cc * 8);
            CP16(d + 3 * AKVARR * 4, vbl + r * S_ + cc * 8);
        }
    };

    // stage Q + first K/V tile as group 0
    {
        const __nv_bfloat16* q_h = qh + (bh * S_ + q0) * DH_;
        const __nv_bfloat16* q_l = ql + (bh * S_ + q0) * DH_;
        #pragma unroll
        for (int l = 0; l < 4; l++) {
            int ci = tid + l * 256;                // 0..1023
            int r = ci >> 3, cc = ci & 7;
            uint32_t d = sbase + (r * ATS + cc * 4) * 4;
            CP16(d + AQH * 4, q_h + r * DH_ + cc * 8);
            CP16(d + AQL * 4, q_l + r * DH_ + cc * 8);
        }
        stageKV(0, 0);
        CP_COMMIT();
    }

    float m0 = -1e30f, m1 = -1e30f, l0 = 0.0f, l1 = 0.0f;
    float acc[8][4];
    #pragma unroll
    for (int nt = 0; nt < 8; nt++)
        #pragma unroll
        for (int q = 0; q < 4; q++) acc[nt][q] = 0.0f;

    const int mrow = wid * 16;
    uint32_t* sQh = sm32 + AQH;
    uint32_t* sQl = sm32 + AQL;

    for (int kt = 0; kt < S_ / 64; kt++) {
        if (kt < S_ / 64 - 1) { stageKV(kt + 1, (kt + 1) & 1); CP_COMMIT(); CP_WAIT1(); }
        else                  { CP_WAIT0(); }
        __syncthreads();

        uint32_t* sKh = sm32 + AKV + (kt & 1) * AKVS;
        uint32_t* sKl = sKh + AKVARR;
        uint32_t* sVh = sKh + 2 * AKVARR;
        uint32_t* sVl = sKh + 3 * AKVARR;

        // ---- QK^T ----
        float sc[8][4];
        #pragma unroll
        for (int nt = 0; nt < 8; nt++)
            #pragma unroll
            for (int q = 0; q < 4; q++) sc[nt][q] = 0.0f;

        #pragma unroll
        for (int ks = 0; ks < 4; ks++) {
            uint32_t ah[4], al[4];
            int a0 = (mrow + g) * ATS + ks * 8 + tig;
            int a1 = (mrow + g + 8) * ATS + ks * 8 + tig;
            ah[0] = sQh[a0]; ah[1] = sQh[a1]; ah[2] = sQh[a0 + 4]; ah[3] = sQh[a1 + 4];
            al[0] = sQl[a0]; al[1] = sQl[a1]; al[2] = sQl[a0 + 4]; al[3] = sQl[a1 + 4];
            #pragma unroll
            for (int nt = 0; nt < 8; nt++) {
                int bb = (nt * 8 + g) * ATS + ks * 8 + tig;
                uint32_t bhf[2] = {sKh[bb], sKh[bb + 4]};
                uint32_t blf[2] = {sKl[bb], sKl[bb + 4]};
                mma16816(sc[nt], ah, bhf);
                mma16816(sc[nt], ah, blf);
                mma16816(sc[nt], al, bhf);
            }
        }

        // ---- online softmax (warp-local) ----
        {
            float mx0 = -1e30f, mx1 = -1e30f;
            #pragma unroll
            for (int nt = 0; nt < 8; nt++) {
                mx0 = fmaxf(mx0, fmaxf(sc[nt][0], sc[nt][1]));
                mx1 = fmaxf(mx1, fmaxf(sc[nt][2], sc[nt][3]));
            }
            mx0 *= 0.125f; mx1 *= 0.125f;
            #pragma unroll
            for (int off = 1; off < 4; off <<= 1) {
                mx0 = fmaxf(mx0, __shfl_xor_sync(0xffffffffu, mx0, off));
                mx1 = fmaxf(mx1, __shfl_xor_sync(0xffffffffu, mx1, off));
            }
            float mn0 = fmaxf(m0, mx0), mn1 = fmaxf(m1, mx1);
            float al0 = __expf(m0 - mn0), al1 = __expf(m1 - mn1);
            float s0 = 0.0f, s1 = 0.0f;
            #pragma unroll
            for (int nt = 0; nt < 8; nt++) {
                sc[nt][0] = __expf(fmaf(sc[nt][0], 0.125f, -mn0));
                sc[nt][1] = __expf(fmaf(sc[nt][1], 0.125f, -mn0));
                sc[nt][2] = __expf(fmaf(sc[nt][2], 0.125f, -mn1));
                sc[nt][3] = __expf(fmaf(sc[nt][3], 0.125f, -mn1));
                s0 += sc[nt][0] + sc[nt][1];
                s1 += sc[nt][2] + sc[nt][3];
            }
            #pragma unroll
            for (int off = 1; off < 4; off <<= 1) {
                s0 += __shfl_xor_sync(0xffffffffu, s0, off);
                s1 += __shfl_xor_sync(0xffffffffu, s1, off);
            }
            l0 = l0 * al0 + s0; l1 = l1 * al1 + s1;
            m0 = mn0; m1 = mn1;
            #pragma unroll
            for (int nt = 0; nt < 8; nt++) {
                acc[nt][0] *= al0; acc[nt][1] *= al0;
                acc[nt][2] *= al1; acc[nt][3] *= al1;
            }
        }

        // ---- P @ V ----
        #pragma unroll
        for (int kk = 0; kk < 4; kk++) {
            float p00 = sc[2*kk][0],   p01 = sc[2*kk][1];
            float p10 = sc[2*kk][2],   p11 = sc[2*kk][3];
            float r00 = sc[2*kk+1][0], r01 = sc[2*kk+1][1];
            float r10 = sc[2*kk+1][2], r11 = sc[2*kk+1][3];
            uint32_t pah[4], pal[4];
            uint16_t h00 = bf16_bits(p00), h01 = bf16_bits(p01);
            uint16_t h10 = bf16_bits(p10), h11 = bf16_bits(p11);
            uint16_t i00 = bf16_bits(r00), i01 = bf16_bits(r01);
            uint16_t i10 = bf16_bits(r10), i11 = bf16_bits(r11);
            pah[0] = (uint32_t)h01 << 16 | h00;
            pah[1] = (uint32_t)h11 << 16 | h10;
            pah[2] = (uint32_t)i01 << 16 | i00;
            pah[3] = (uint32_t)i11 << 16 | i10;
            pal[0] = pack_bf16x2(p00 - bf16_val(h00), p01 - bf16_val(h01));
            pal[1] = pack_bf16x2(p10 - bf16_val(h10), p11 - bf16_val(h11));
            pal[2] = pack_bf16x2(r00 - bf16_val(i00), r01 - bf16_val(i01));
            pal[3] = pack_bf16x2(r10 - bf16_val(i10), r11 - bf16_val(i11));
            #pragma unroll
            for (int nt = 0; nt < 8; nt++) {
                int bb = (nt * 8 + g) * ATS + kk * 8 + tig;
                uint32_t vhf[2] = {sVh[bb], sVh[bb + 4]};
                uint32_t vlf[2] = {sVl[bb], sVl[bb + 4]};
                mma16816(acc[nt], pah, vhf);
                mma16816(acc[nt], pah, vlf);
                mma16816(acc[nt], pal, vhf);
            }
        }
        __syncthreads();
    }

    // ---- epilogue ----
    {
        const int b = bh >> 4, h = bh & 15;
        float inv0 = 1.0f / l0, inv1 = 1.0f / l1;
        int r0 = q0 + mrow + g, r1 = r0 + 8;
        #pragma unroll
        for (int nt = 0; nt < 8; nt++) {
            int col = nt * 8 + 2 * tig;
            float2 o0 = {acc[nt][0] * inv0, acc[nt][1] * inv0};
            float2 o1 = {acc[nt][2] * inv1, acc[nt][3] * inv1};
            *reinterpret_cast<float2*>(out + (b * S_ + r0) * D_ + h * DH_ + col) = o0;
            *reinterpret_cast<float2*>(out + (b * S_ + r1) * D_ + h * DH_ + col) = o1;
        }
    }
}

// ---------------------------------------------------------------------------
extern "C" void kernel_launch(void* const* d_in, const int* in_sizes, int n_in,
                              void* d_out, int out_size)
{
    const float* vq = (const float*)d_in[0];
    const float* vk = (const float*)d_in[1];
    const float* vv = (const float*)d_in[2];
    const float* wq = (const float*)d_in[3];
    const float* bq = (const float*)d_in[4];
    const float* wk = (const float*)d_in[5];
    const float* bk = (const float*)d_in[6];
    const float* wv = (const float*)d_in[7];
    const float* bv = (const float*)d_in[8];
    float* out = (float*)d_out;

    // 1. pre-split inputs + transpose-split weights
    dim3 gx(NROW * D_ / 1024, 3);
    xsplit_kernel<<<gx, 256>>>(vq, vk, vv);
    dim3 gw(D_ / 32, D_ / 32, 3);
    wsplit_kernel<<<gw, 256>>>(wq, wk, wv);

    // 2. projections (fused 3-in-1, double-buffered)
    cudaFuncSetAttribute(proj_mma_kernel,
                         cudaFuncAttributeMaxDynamicSharedMemorySize, PROJ_SMEM_BYTES);
    dim3 grid_p(D_ / 128, NROW / 128, 3);   // (8, 32, 3)
    proj_mma_kernel<<<grid_p, 256, PROJ_SMEM_BYTES>>>(bq, bk, bv);

    // 3. attention
    cudaFuncSetAttribute(attn_mma_kernel,
                         cudaFuncAttributeMaxDynamicSharedMemorySize, ATT_SMEM_BYTES);
    dim3 grid_a(S_ / 128, B_ * H_);         // (16, 32)
    attn_mma_kernel<<<grid_a, 256, ATT_SMEM_BYTES>>>(out);
}